// round 2
// baseline (speedup 1.0000x reference)
#include <cuda_runtime.h>
#include <cuda_bf16.h>
#include <cstdint>
#include <math.h>

#define Bz 32
#define Nn 128
#define Ee 16384
#define NP 36
#define M_EDGES (Bz*Ee)   /* 524288 */
#define M_NODES (Bz*Nn)   /* 4096   */

typedef unsigned long long u64;

// ---------------- scratch (static device globals; no runtime allocs) ---------
__device__ float g_P[M_NODES*72];
__device__ float g_Q[M_NODES*72];
__device__ float g_gx[M_EDGES];
__device__ float g_magg[M_NODES*72];
__device__ float g_z2[M_NODES*72];
__device__ float g_part1s[72*512];
__device__ float g_part1q[72*512];
__device__ float g_part2s[72*128];
__device__ float g_part2q[72*128];
__device__ float g_bn1[144];
__device__ float g_bn2[144];

// ---------------- packed fp32x2 helpers (Blackwell) ---------------------------
__device__ __forceinline__ u64 ffma2(u64 a, u64 b, u64 c){
    u64 d; asm("fma.rn.f32x2 %0,%1,%2,%3;" : "=l"(d) : "l"(a), "l"(b), "l"(c)); return d;
}
__device__ __forceinline__ u64 fadd2(u64 a, u64 b){
    u64 d; asm("add.rn.f32x2 %0,%1,%2;" : "=l"(d) : "l"(a), "l"(b)); return d;
}
__device__ __forceinline__ u64 mul2(u64 a, u64 b){
    u64 d; asm("mul.rn.f32x2 %0,%1,%2;" : "=l"(d) : "l"(a), "l"(b)); return d;
}
__device__ __forceinline__ u64 dup2(float x){
    u64 d; unsigned r = __float_as_uint(x);
    asm("mov.b64 %0,{%1,%1};" : "=l"(d) : "r"(r)); return d;
}
__device__ __forceinline__ u64 pack2(float a, float b){
    u64 d; asm("mov.b64 %0,{%1,%2};" : "=l"(d) : "r"(__float_as_uint(a)), "r"(__float_as_uint(b))); return d;
}
__device__ __forceinline__ float2 unpack2(u64 v){
    unsigned lo, hi; asm("mov.b64 {%0,%1},%2;" : "=r"(lo), "=r"(hi) : "l"(v));
    return make_float2(__uint_as_float(lo), __uint_as_float(hi));
}
__device__ __forceinline__ float psi_f(float p){
    return copysignf(log1pf(fabsf(p)), p);
}
__device__ __forceinline__ float wred(float v){
#pragma unroll
    for (int o = 16; o; o >>= 1) v += __shfl_xor_sync(0xffffffffu, v, o);
    return v;
}

// ---------------- K1: P = h @ We1[0:72], Q = h @ We1[72:144] -------------------
__global__ void __launch_bounds__(256) k_pq(const float* __restrict__ h,
                                            const float* __restrict__ We1){
    __shared__ float sW[144*72];
    for (int t = threadIdx.x; t < 144*72; t += 256) sW[t] = We1[t];
    __syncthreads();
    int node = blockIdx.x*256 + threadIdx.x;
    const u64* Wu = (const u64*)sW;
    const float* hr = h + (size_t)node*72;
    u64 acc[NP];
#pragma unroll
    for (int p = 0; p < NP; p++) acc[p] = 0ull;
#pragma unroll 4
    for (int k = 0; k < 72; k++){
        u64 f = dup2(hr[k]);
        const u64* row = Wu + k*NP;
#pragma unroll
        for (int p = 0; p < NP; p++) acc[p] = ffma2(f, row[p], acc[p]);
    }
    u64* o = (u64*)(g_P + (size_t)node*72);
#pragma unroll
    for (int p = 0; p < NP; p++) o[p] = acc[p];
#pragma unroll
    for (int p = 0; p < NP; p++) acc[p] = 0ull;
#pragma unroll 4
    for (int k = 0; k < 72; k++){
        u64 f = dup2(hr[k]);
        const u64* row = Wu + (72 + k)*NP;
#pragma unroll
        for (int p = 0; p < NP; p++) acc[p] = ffma2(f, row[p], acc[p]);
    }
    o = (u64*)(g_Q + (size_t)node*72);
#pragma unroll
    for (int p = 0; p < NP; p++) o[p] = acc[p];
}

// ---------------- K2: BN1 statistics (per-block partials, deterministic) ------
__global__ void __launch_bounds__(256) k_stats1(const float* __restrict__ x,
                                                const int* __restrict__ ei_all,
                                                const int* __restrict__ ej_all,
                                                const float* __restrict__ We1){
    extern __shared__ char smraw[];
    u64*   Ps   = (u64*)smraw;          // 4608 u64
    u64*   Qs   = Ps + 4608;            // 4608 u64
    float* xs   = (float*)(Qs + 4608);  // 640
    float* w144 = xs + 640;             // 72
    float* w145 = w144 + 72;            // 72
    float* sred = w145 + 72;            // 576
    float* sredq= sred + 576;           // 576

    int tid = threadIdx.x;
    int b = blockIdx.x >> 4, chunk = blockIdx.x & 15;

    const u64* Pg = (const u64*)g_P + (size_t)b*Nn*NP;
    const u64* Qg = (const u64*)g_Q + (size_t)b*Nn*NP;
    for (int t = tid; t < Nn*NP; t += 256){
        int i = t / NP, p = t - i*NP;
        Ps[p*Nn + i] = Pg[t];
        Qs[p*Nn + i] = Qg[t];
    }
    for (int t = tid; t < 512; t += 256) xs[(t>>2)*5 + (t&3)] = x[b*512 + t];
    for (int t = tid; t < 72; t += 256){
        w144[t] = We1[144*72 + t];
        w145[t] = We1[145*72 + t];
    }
    __syncthreads();
    const u64* w144u = (const u64*)w144;
    const u64* w145u = (const u64*)w145;

    u64 sum[NP], ssq[NP];
#pragma unroll
    for (int p = 0; p < NP; p++){ sum[p] = 0ull; ssq[p] = 0ull; }

    for (int it = 0; it < 4; it++){
        int ge = (b<<14) + (chunk<<10) + (it<<8) + tid;
        int i = ei_all[ge], j = ej_all[ge];
        float xi0=xs[i*5],xi1=xs[i*5+1],xi2=xs[i*5+2],xi3=xs[i*5+3];
        float xj0=xs[j*5],xj1=xs[j*5+1],xj2=xs[j*5+2],xj3=xs[j*5+3];
        float d0=xi0-xj0,d1=xi1-xj1,d2=xi2-xj2,d3=xi3-xj3;
        u64 dn = dup2(psi_f(d0*d0 - d1*d1 - d2*d2 - d3*d3));
        u64 dd = dup2(psi_f(xi0*xj0 - xi1*xj1 - xi2*xj2 - xi3*xj3));
#pragma unroll
        for (int p = 0; p < NP; p++){
            u64 z = fadd2(Ps[p*Nn + i], Qs[p*Nn + j]);
            z = ffma2(dn, w144u[p], z);
            z = ffma2(dd, w145u[p], z);
            sum[p] = fadd2(sum[p], z);
            ssq[p] = ffma2(z, z, ssq[p]);
        }
    }
    int lane = tid & 31, wid = tid >> 5;
#pragma unroll
    for (int p = 0; p < NP; p++){
        float2 s = unpack2(sum[p]), q = unpack2(ssq[p]);
        float s0 = wred(s.x), s1 = wred(s.y), q0 = wred(q.x), q1 = wred(q.y);
        if (lane == 0){
            sred [wid*72 + 2*p]   = s0; sred [wid*72 + 2*p+1] = s1;
            sredq[wid*72 + 2*p]   = q0; sredq[wid*72 + 2*p+1] = q1;
        }
    }
    __syncthreads();
    if (tid < 72){
        float S = 0.f, Q = 0.f;
        for (int w = 0; w < 8; w++){ S += sred[w*72 + tid]; Q += sredq[w*72 + tid]; }
        g_part1s[tid*512 + blockIdx.x] = S;
        g_part1q[tid*512 + blockIdx.x] = Q;
    }
}

// ---------------- K3: finalize BN1 ---------------------------------------------
__global__ void k_red1(const float* __restrict__ g1, const float* __restrict__ b1){
    __shared__ float ss[256], sq[256];
    int c = blockIdx.x, t = threadIdx.x;
    ss[t] = g_part1s[c*512 + t] + g_part1s[c*512 + 256 + t];
    sq[t] = g_part1q[c*512 + t] + g_part1q[c*512 + 256 + t];
    __syncthreads();
    for (int o = 128; o; o >>= 1){
        if (t < o){ ss[t] += ss[t+o]; sq[t] += sq[t+o]; }
        __syncthreads();
    }
    if (t == 0){
        float inv = 1.f / (float)M_EDGES;
        float mu = ss[0]*inv;
        float var = sq[0]*inv - mu*mu;
        float sc = g1[c]*rsqrtf(var + 1e-5f);
        g_bn1[c] = sc;
        g_bn1[72 + c] = b1[c] - mu*sc;
    }
}

// ---------------- K4: main edge kernel -----------------------------------------
__global__ void __launch_bounds__(256,1) k_edge(
    const float* __restrict__ x, const int* __restrict__ ei_all, const int* __restrict__ ej_all,
    const float* __restrict__ We1, const float* __restrict__ We2, const float* __restrict__ be2,
    const float* __restrict__ Wm, const float* __restrict__ bm,
    const float* __restrict__ Wx1, const float* __restrict__ bx1, const float* __restrict__ Wx2,
    float* __restrict__ out_m)
{
    extern __shared__ char smraw[];
    u64*   Ps   = (u64*)smraw;          // 4608
    u64*   Qs   = Ps + 4608;            // 4608
    float* xs   = (float*)(Qs + 4608);  // 640
    float* w144 = xs + 640;             // 72
    float* w145 = w144 + 72;            // 72
    float* sWe2 = w145 + 72;            // 5184
    float* sWx1 = sWe2 + 5184;          // 5184
    float* sbn  = sWx1 + 5184;          // 144
    float* sbe2 = sbn + 144;            // 72
    float* sWm  = sbe2 + 72;            // 72
    float* sbx1 = sWm + 72;             // 72
    float* sWx2 = sbx1 + 72;            // 72
    float* s_act= sWx2 + 72;            // 72*257

    int tid = threadIdx.x;
    int b = blockIdx.x >> 4, chunk = blockIdx.x & 15;

    const u64* Pg = (const u64*)g_P + (size_t)b*Nn*NP;
    const u64* Qg = (const u64*)g_Q + (size_t)b*Nn*NP;
    for (int t = tid; t < Nn*NP; t += 256){
        int i = t / NP, p = t - i*NP;
        Ps[p*Nn + i] = Pg[t];
        Qs[p*Nn + i] = Qg[t];
    }
    for (int t = tid; t < 512; t += 256) xs[(t>>2)*5 + (t&3)] = x[b*512 + t];
    for (int t = tid; t < 72; t += 256){
        w144[t] = We1[144*72 + t]; w145[t] = We1[145*72 + t];
        sbe2[t] = be2[t]; sWm[t] = Wm[t]; sbx1[t] = bx1[t]; sWx2[t] = Wx2[t];
    }
    for (int t = tid; t < 5184; t += 256){ sWe2[t] = We2[t]; sWx1[t] = Wx1[t]; }
    for (int t = tid; t < 144; t += 256) sbn[t] = g_bn1[t];
    __syncthreads();

    const u64* w144u = (const u64*)w144;
    const u64* w145u = (const u64*)w145;
    const u64* We2u  = (const u64*)sWe2;
    const u64* Wx1u  = (const u64*)sWx1;
    const u64* be2u  = (const u64*)sbe2;
    const u64* bx1u  = (const u64*)sbx1;
    float bm0 = bm[0];

    for (int it = 0; it < 4; it++){
        int ge = (b<<14) + (chunk<<10) + (it<<8) + tid;
        int i = ei_all[ge], j = ej_all[ge];
        float xi0=xs[i*5],xi1=xs[i*5+1],xi2=xs[i*5+2],xi3=xs[i*5+3];
        float xj0=xs[j*5],xj1=xs[j*5+1],xj2=xs[j*5+2],xj3=xs[j*5+3];
        float d0=xi0-xj0,d1=xi1-xj1,d2=xi2-xj2,d3=xi3-xj3;
        u64 dn = dup2(psi_f(d0*d0 - d1*d1 - d2*d2 - d3*d3));
        u64 dd = dup2(psi_f(xi0*xj0 - xi1*xj1 - xi2*xj2 - xi3*xj3));

        // z1 -> BN1 -> relu -> s_act
#pragma unroll
        for (int p = 0; p < NP; p++){
            u64 z = fadd2(Ps[p*Nn + i], Qs[p*Nn + j]);
            z = ffma2(dn, w144u[p], z);
            z = ffma2(dd, w145u[p], z);
            float2 v = unpack2(z);
            s_act[(2*p)*257 + tid]   = fmaxf(fmaf(v.x, sbn[2*p],   sbn[72+2*p]),   0.f);
            s_act[(2*p+1)*257 + tid] = fmaxf(fmaf(v.y, sbn[2*p+1], sbn[72+2*p+1]), 0.f);
        }

        // z2 = a @ We2 + be2
        u64 acc[NP];
#pragma unroll
        for (int p = 0; p < NP; p++) acc[p] = be2u[p];
#pragma unroll 4
        for (int k = 0; k < 72; k++){
            u64 f = dup2(s_act[k*257 + tid]);
            const u64* row = We2u + k*NP;
#pragma unroll
            for (int p = 0; p < NP; p++) acc[p] = ffma2(f, row[p], acc[p]);
        }
        // relu -> m0, gate t = m0 . Wm + bm
        float t = bm0;
#pragma unroll
        for (int p = 0; p < NP; p++){
            float2 v = unpack2(acc[p]);
            float a0 = fmaxf(v.x, 0.f), a1 = fmaxf(v.y, 0.f);
            t = fmaf(a0, sWm[2*p], t);
            t = fmaf(a1, sWm[2*p+1], t);
            acc[p] = pack2(a0, a1);
        }
        float sg = 1.f / (1.f + __expf(-t));
        u64 sg2 = dup2(sg);
        // m = m0 * sigmoid -> s_act (also kept there for output drain)
#pragma unroll
        for (int p = 0; p < NP; p++){
            u64 mv = mul2(acc[p], sg2);
            float2 v = unpack2(mv);
            s_act[(2*p)*257 + tid]   = v.x;
            s_act[(2*p+1)*257 + tid] = v.y;
        }

        // w = m @ Wx1 + bx1
#pragma unroll
        for (int p = 0; p < NP; p++) acc[p] = bx1u[p];
#pragma unroll 4
        for (int k = 0; k < 72; k++){
            u64 f = dup2(s_act[k*257 + tid]);
            const u64* row = Wx1u + k*NP;
#pragma unroll
            for (int p = 0; p < NP; p++) acc[p] = ffma2(f, row[p], acc[p]);
        }
        float gx = 0.f;
#pragma unroll
        for (int p = 0; p < NP; p++){
            float2 v = unpack2(acc[p]);
            gx = fmaf(fmaxf(v.x, 0.f), sWx2[2*p],   gx);
            gx = fmaf(fmaxf(v.y, 0.f), sWx2[2*p+1], gx);
        }
        g_gx[ge] = gx;

        // coalesced drain of m to gmem
        __syncthreads();
        {
            float* dst = out_m + ((size_t)((b<<14) + (chunk<<10) + (it<<8)))*72;
            int c = tid % 72, e = tid / 72;
            for (int s = tid; s < 72*256; s += 256){
                dst[e*72 + c] = s_act[c*257 + e];
                c += 40; e += 3;
                if (c >= 72){ c -= 72; e += 1; }
            }
        }
        __syncthreads();
    }
}

// ---------------- K5: segment aggregation (warp per node, deterministic) ------
__global__ void __launch_bounds__(256) k_agg(const float* __restrict__ x,
                                             const int* __restrict__ ei_all,
                                             const int* __restrict__ ej_all,
                                             const float* __restrict__ out_m,
                                             float* __restrict__ out_x){
    __shared__ float xs[512];
    int b = blockIdx.x >> 4;
    int wid = threadIdx.x >> 5, lane = threadIdx.x & 31;
    int node = ((blockIdx.x & 15) << 3) + wid;
    for (int t = threadIdx.x; t < 512; t += 256) xs[t] = x[b*512 + t];
    __syncthreads();
    const int* ei = ei_all + b*Ee;
    const int* ej = ej_all + b*Ee;
    const float* mb = out_m + (size_t)b*Ee*72;
    const float* gxb = g_gx + b*Ee;

    float m0=0.f, m1=0.f, m2=0.f;
    float xa0=0.f, xa1=0.f, xa2=0.f, xa3=0.f;
    int cnt = 0;
    float xi0=xs[node*4], xi1=xs[node*4+1], xi2=xs[node*4+2], xi3=xs[node*4+3];

    int ii = ei[lane];
    for (int base = 0; base < Ee; base += 32){
        int nxt = (base + 32 < Ee) ? ei[base + 32 + lane] : 0;
        unsigned msk = __ballot_sync(0xffffffffu, ii == node);
        cnt += __popc(msk);
        while (msk){
            int bit = __ffs(msk) - 1; msk &= msk - 1;
            int e = base + bit;
            const float* mr = mb + (size_t)e*72;
            m0 += mr[lane];
            m1 += mr[32 + lane];
            if (lane < 8) m2 += mr[64 + lane];
            float g = gxb[e];
            int j = ej[e];
            xa0 += fminf(fmaxf((xi0 - xs[j*4+0])*g, -100.f), 100.f);
            xa1 += fminf(fmaxf((xi1 - xs[j*4+1])*g, -100.f), 100.f);
            xa2 += fminf(fmaxf((xi2 - xs[j*4+2])*g, -100.f), 100.f);
            xa3 += fminf(fmaxf((xi3 - xs[j*4+3])*g, -100.f), 100.f);
        }
        ii = nxt;
    }
    float* mg = g_magg + (size_t)(b*Nn + node)*72;
    mg[lane] = m0;
    mg[32 + lane] = m1;
    if (lane < 8) mg[64 + lane] = m2;
    if (lane == 0){
        float d = fmaxf((float)cnt, 1.f);
        float* xo = out_x + (size_t)(b*Nn + node)*4;
        xo[0] = xi0 + xa0/d;
        xo[1] = xi1 + xa1/d;
        xo[2] = xi2 + xa2/d;
        xo[3] = xi3 + xa3/d;
    }
}

// ---------------- K6: z2pre = [h, magg, attr] @ Wh1 + bh1; BN2 partials --------
__global__ void __launch_bounds__(256) k_stats2(const float* __restrict__ h,
                                                const float* __restrict__ na,
                                                const float* __restrict__ Wh1,
                                                const float* __restrict__ bh1){
    __shared__ float sW[148*72];
    for (int t = threadIdx.x; t < 148*72; t += 256) sW[t] = Wh1[t];
    __syncthreads();
    int node = blockIdx.x*256 + threadIdx.x;
    const u64* Wu = (const u64*)sW;
    const u64* bu = (const u64*)bh1;
    u64 acc[NP];
#pragma unroll
    for (int p = 0; p < NP; p++) acc[p] = bu[p];
    const float* hr = h + (size_t)node*72;
#pragma unroll 4
    for (int k = 0; k < 72; k++){
        u64 f = dup2(hr[k]);
        const u64* row = Wu + k*NP;
#pragma unroll
        for (int p = 0; p < NP; p++) acc[p] = ffma2(f, row[p], acc[p]);
    }
    const float* mr = g_magg + (size_t)node*72;
#pragma unroll 4
    for (int k = 0; k < 72; k++){
        u64 f = dup2(mr[k]);
        const u64* row = Wu + (72 + k)*NP;
#pragma unroll
        for (int p = 0; p < NP; p++) acc[p] = ffma2(f, row[p], acc[p]);
    }
    const float* ar = na + (size_t)node*4;
#pragma unroll
    for (int k = 0; k < 4; k++){
        u64 f = dup2(ar[k]);
        const u64* row = Wu + (144 + k)*NP;
#pragma unroll
        for (int p = 0; p < NP; p++) acc[p] = ffma2(f, row[p], acc[p]);
    }
    u64* zo = (u64*)(g_z2 + (size_t)node*72);
#pragma unroll
    for (int p = 0; p < NP; p++) zo[p] = acc[p];

    int lane = threadIdx.x & 31, wid = threadIdx.x >> 5;
    int gw = blockIdx.x*8 + wid;
#pragma unroll
    for (int p = 0; p < NP; p++){
        float2 v = unpack2(acc[p]);
        float s0 = wred(v.x), s1 = wred(v.y);
        float q0 = wred(v.x*v.x), q1 = wred(v.y*v.y);
        if (lane == 0){
            g_part2s[(2*p)*128 + gw] = s0; g_part2s[(2*p+1)*128 + gw] = s1;
            g_part2q[(2*p)*128 + gw] = q0; g_part2q[(2*p+1)*128 + gw] = q1;
        }
    }
}

// ---------------- K7: finalize BN2 ---------------------------------------------
__global__ void k_red2(const float* __restrict__ gh, const float* __restrict__ bh){
    __shared__ float ss[128], sq[128];
    int c = blockIdx.x, t = threadIdx.x;
    ss[t] = g_part2s[c*128 + t];
    sq[t] = g_part2q[c*128 + t];
    __syncthreads();
    for (int o = 64; o; o >>= 1){
        if (t < o){ ss[t] += ss[t+o]; sq[t] += sq[t+o]; }
        __syncthreads();
    }
    if (t == 0){
        float inv = 1.f/4096.f;
        float mu = ss[0]*inv;
        float var = sq[0]*inv - mu*mu;
        float sc = gh[c]*rsqrtf(var + 1e-5f);
        g_bn2[c] = sc;
        g_bn2[72 + c] = bh[c] - mu*sc;
    }
}

// ---------------- K8: h_out -----------------------------------------------------
__global__ void __launch_bounds__(256) k_h(const float* __restrict__ h,
                                           const float* __restrict__ Wh2,
                                           const float* __restrict__ bh2,
                                           float* __restrict__ out_h){
    extern __shared__ char smraw[];
    float* sW   = (float*)smraw;   // 5184
    float* sbn  = sW + 5184;       // 144
    float* sb2  = sbn + 144;       // 72
    float* s_act= sb2 + 72;        // 72*257
    int tid = threadIdx.x;
    for (int t = tid; t < 5184; t += 256) sW[t] = Wh2[t];
    for (int t = tid; t < 144; t += 256) sbn[t] = g_bn2[t];
    for (int t = tid; t < 72; t += 256) sb2[t] = bh2[t];
    __syncthreads();
    int node = blockIdx.x*256 + tid;
    const float* zr = g_z2 + (size_t)node*72;
#pragma unroll 4
    for (int c = 0; c < 72; c++)
        s_act[c*257 + tid] = fmaxf(fmaf(zr[c], sbn[c], sbn[72+c]), 0.f);
    const u64* Wu = (const u64*)sW;
    const u64* bu = (const u64*)sb2;
    u64 acc[NP];
#pragma unroll
    for (int p = 0; p < NP; p++) acc[p] = bu[p];
#pragma unroll 4
    for (int k = 0; k < 72; k++){
        u64 f = dup2(s_act[k*257 + tid]);
        const u64* row = Wu + k*NP;
#pragma unroll
        for (int p = 0; p < NP; p++) acc[p] = ffma2(f, row[p], acc[p]);
    }
    const float* hr = h + (size_t)node*72;
    float* o = out_h + (size_t)node*72;
#pragma unroll
    for (int p = 0; p < NP; p++){
        float2 v = unpack2(acc[p]);
        o[2*p]   = hr[2*p]   + v.x;
        o[2*p+1] = hr[2*p+1] + v.y;
    }
}

// ---------------- launch ---------------------------------------------------------
#define SMEM_STATS1 81472
#define SMEM_EDGE   194368
#define SMEM_H      95616

extern "C" void kernel_launch(void* const* d_in, const int* in_sizes, int n_in,
                              void* d_out, int out_size){
    const float* h   = (const float*)d_in[0];
    const float* x   = (const float*)d_in[1];
    const int*   ei  = (const int*)d_in[2];
    const int*   ej  = (const int*)d_in[3];
    const float* na  = (const float*)d_in[4];
    const float* We1 = (const float*)d_in[5];
    const float* g1  = (const float*)d_in[6];
    const float* b1  = (const float*)d_in[7];
    const float* We2 = (const float*)d_in[8];
    const float* be2 = (const float*)d_in[9];
    const float* Wm  = (const float*)d_in[10];
    const float* bm  = (const float*)d_in[11];
    const float* Wx1 = (const float*)d_in[12];
    const float* bx1 = (const float*)d_in[13];
    const float* Wx2 = (const float*)d_in[14];
    const float* Wh1 = (const float*)d_in[15];
    const float* bh1 = (const float*)d_in[16];
    const float* gh  = (const float*)d_in[17];
    const float* bh  = (const float*)d_in[18];
    const float* Wh2 = (const float*)d_in[19];
    const float* bh2 = (const float*)d_in[20];

    float* out   = (float*)d_out;
    float* out_h = out;                 // [B,N,72]
    float* out_x = out + 294912;        // [B,N,4]
    float* out_m = out + 311296;        // [B,E,72]

    cudaFuncSetAttribute(k_stats1, cudaFuncAttributeMaxDynamicSharedMemorySize, SMEM_STATS1);
    cudaFuncSetAttribute(k_edge,   cudaFuncAttributeMaxDynamicSharedMemorySize, SMEM_EDGE);
    cudaFuncSetAttribute(k_h,      cudaFuncAttributeMaxDynamicSharedMemorySize, SMEM_H);

    k_pq    <<<16, 256>>>(h, We1);
    k_stats1<<<512, 256, SMEM_STATS1>>>(x, ei, ej, We1);
    k_red1  <<<72, 256>>>(g1, b1);
    k_edge  <<<512, 256, SMEM_EDGE>>>(x, ei, ej, We1, We2, be2, Wm, bm, Wx1, bx1, Wx2, out_m);
    k_agg   <<<512, 256>>>(x, ei, ej, out_m, out_x);
    k_stats2<<<16, 256>>>(h, na, Wh1, bh1);
    k_red2  <<<72, 128>>>(gh, bh);
    k_h     <<<16, 256, SMEM_H>>>(h, Wh2, bh2, out_h);
}

// round 3
// speedup vs baseline: 1.1876x; 1.1876x over previous
#include <cuda_runtime.h>
#include <cuda_bf16.h>
#include <cstdint>
#include <math.h>

#define Bz 32
#define Nn 128
#define Ee 16384
#define NP 36
#define M_EDGES (Bz*Ee)   /* 524288 */
#define M_NODES (Bz*Nn)   /* 4096   */

typedef unsigned long long u64;

// ---------------- scratch (static device globals; no runtime allocs) ---------
__device__ float g_P[M_NODES*72];
__device__ float g_Q[M_NODES*72];
__device__ float g_gx[M_EDGES];
__device__ float g_magg[M_NODES*72];
__device__ float g_z2[M_NODES*72];
__device__ float g_part1s[72*512];
__device__ float g_part1q[72*512];
__device__ float g_part2s[72*128];
__device__ float g_part2q[72*128];
__device__ float g_bn1[144];
__device__ float g_bn2[144];
__device__ float g_aggp[M_NODES*4*80];   // per (node, quarter-chunk) partials

// ---------------- packed fp32x2 helpers (Blackwell) ---------------------------
__device__ __forceinline__ u64 ffma2(u64 a, u64 b, u64 c){
    u64 d; asm("fma.rn.f32x2 %0,%1,%2,%3;" : "=l"(d) : "l"(a), "l"(b), "l"(c)); return d;
}
__device__ __forceinline__ u64 fadd2(u64 a, u64 b){
    u64 d; asm("add.rn.f32x2 %0,%1,%2;" : "=l"(d) : "l"(a), "l"(b)); return d;
}
__device__ __forceinline__ u64 mul2(u64 a, u64 b){
    u64 d; asm("mul.rn.f32x2 %0,%1,%2;" : "=l"(d) : "l"(a), "l"(b)); return d;
}
__device__ __forceinline__ u64 dup2(float x){
    u64 d; unsigned r = __float_as_uint(x);
    asm("mov.b64 %0,{%1,%1};" : "=l"(d) : "r"(r)); return d;
}
__device__ __forceinline__ u64 pack2(float a, float b){
    u64 d; asm("mov.b64 %0,{%1,%2};" : "=l"(d) : "r"(__float_as_uint(a)), "r"(__float_as_uint(b))); return d;
}
__device__ __forceinline__ float2 unpack2(u64 v){
    unsigned lo, hi; asm("mov.b64 {%0,%1},%2;" : "=r"(lo), "=r"(hi) : "l"(v));
    return make_float2(__uint_as_float(lo), __uint_as_float(hi));
}
__device__ __forceinline__ float psi_f(float p){
    return copysignf(log1pf(fabsf(p)), p);
}
__device__ __forceinline__ float wred(float v){
#pragma unroll
    for (int o = 16; o; o >>= 1) v += __shfl_xor_sync(0xffffffffu, v, o);
    return v;
}

// ---------------- K1: P = h @ We1[0:72], Q = h @ We1[72:144] -------------------
__global__ void __launch_bounds__(256) k_pq(const float* __restrict__ h,
                                            const float* __restrict__ We1){
    __shared__ float sW[144*72];
    for (int t = threadIdx.x; t < 144*72; t += 256) sW[t] = We1[t];
    __syncthreads();
    int node = blockIdx.x*256 + threadIdx.x;
    const u64* Wu = (const u64*)sW;
    const float* hr = h + (size_t)node*72;
    u64 acc[NP];
#pragma unroll
    for (int p = 0; p < NP; p++) acc[p] = 0ull;
#pragma unroll 4
    for (int k = 0; k < 72; k++){
        u64 f = dup2(hr[k]);
        const u64* row = Wu + k*NP;
#pragma unroll
        for (int p = 0; p < NP; p++) acc[p] = ffma2(f, row[p], acc[p]);
    }
    u64* o = (u64*)(g_P + (size_t)node*72);
#pragma unroll
    for (int p = 0; p < NP; p++) o[p] = acc[p];
#pragma unroll
    for (int p = 0; p < NP; p++) acc[p] = 0ull;
#pragma unroll 4
    for (int k = 0; k < 72; k++){
        u64 f = dup2(hr[k]);
        const u64* row = Wu + (72 + k)*NP;
#pragma unroll
        for (int p = 0; p < NP; p++) acc[p] = ffma2(f, row[p], acc[p]);
    }
    o = (u64*)(g_Q + (size_t)node*72);
#pragma unroll
    for (int p = 0; p < NP; p++) o[p] = acc[p];
}

// ---------------- K2: BN1 statistics (per-block partials, deterministic) ------
__global__ void __launch_bounds__(256) k_stats1(const float* __restrict__ x,
                                                const int* __restrict__ ei_all,
                                                const int* __restrict__ ej_all,
                                                const float* __restrict__ We1){
    extern __shared__ char smraw[];
    u64*   Ps   = (u64*)smraw;          // 4608 u64
    u64*   Qs   = Ps + 4608;            // 4608 u64
    float* xs   = (float*)(Qs + 4608);  // 640
    float* w144 = xs + 640;             // 72
    float* w145 = w144 + 72;            // 72
    float* sred = w145 + 72;            // 576
    float* sredq= sred + 576;           // 576

    int tid = threadIdx.x;
    int b = blockIdx.x >> 4, chunk = blockIdx.x & 15;

    const u64* Pg = (const u64*)g_P + (size_t)b*Nn*NP;
    const u64* Qg = (const u64*)g_Q + (size_t)b*Nn*NP;
    for (int t = tid; t < Nn*NP; t += 256){
        int i = t / NP, p = t - i*NP;
        Ps[p*Nn + i] = Pg[t];
        Qs[p*Nn + i] = Qg[t];
    }
    for (int t = tid; t < 512; t += 256) xs[(t>>2)*5 + (t&3)] = x[b*512 + t];
    for (int t = tid; t < 72; t += 256){
        w144[t] = We1[144*72 + t];
        w145[t] = We1[145*72 + t];
    }
    __syncthreads();
    const u64* w144u = (const u64*)w144;
    const u64* w145u = (const u64*)w145;

    u64 sum[NP], ssq[NP];
#pragma unroll
    for (int p = 0; p < NP; p++){ sum[p] = 0ull; ssq[p] = 0ull; }

    for (int it = 0; it < 4; it++){
        int ge = (b<<14) + (chunk<<10) + (it<<8) + tid;
        int i = ei_all[ge], j = ej_all[ge];
        float xi0=xs[i*5],xi1=xs[i*5+1],xi2=xs[i*5+2],xi3=xs[i*5+3];
        float xj0=xs[j*5],xj1=xs[j*5+1],xj2=xs[j*5+2],xj3=xs[j*5+3];
        float d0=xi0-xj0,d1=xi1-xj1,d2=xi2-xj2,d3=xi3-xj3;
        u64 dn = dup2(psi_f(d0*d0 - d1*d1 - d2*d2 - d3*d3));
        u64 dd = dup2(psi_f(xi0*xj0 - xi1*xj1 - xi2*xj2 - xi3*xj3));
#pragma unroll
        for (int p = 0; p < NP; p++){
            u64 z = fadd2(Ps[p*Nn + i], Qs[p*Nn + j]);
            z = ffma2(dn, w144u[p], z);
            z = ffma2(dd, w145u[p], z);
            sum[p] = fadd2(sum[p], z);
            ssq[p] = ffma2(z, z, ssq[p]);
        }
    }
    int lane = tid & 31, wid = tid >> 5;
#pragma unroll
    for (int p = 0; p < NP; p++){
        float2 s = unpack2(sum[p]), q = unpack2(ssq[p]);
        float s0 = wred(s.x), s1 = wred(s.y), q0 = wred(q.x), q1 = wred(q.y);
        if (lane == 0){
            sred [wid*72 + 2*p]   = s0; sred [wid*72 + 2*p+1] = s1;
            sredq[wid*72 + 2*p]   = q0; sredq[wid*72 + 2*p+1] = q1;
        }
    }
    __syncthreads();
    if (tid < 72){
        float S = 0.f, Q = 0.f;
        for (int w = 0; w < 8; w++){ S += sred[w*72 + tid]; Q += sredq[w*72 + tid]; }
        g_part1s[tid*512 + blockIdx.x] = S;
        g_part1q[tid*512 + blockIdx.x] = Q;
    }
}

// ---------------- K3: finalize BN1 ---------------------------------------------
__global__ void k_red1(const float* __restrict__ g1, const float* __restrict__ b1){
    __shared__ float ss[256], sq[256];
    int c = blockIdx.x, t = threadIdx.x;
    ss[t] = g_part1s[c*512 + t] + g_part1s[c*512 + 256 + t];
    sq[t] = g_part1q[c*512 + t] + g_part1q[c*512 + 256 + t];
    __syncthreads();
    for (int o = 128; o; o >>= 1){
        if (t < o){ ss[t] += ss[t+o]; sq[t] += sq[t+o]; }
        __syncthreads();
    }
    if (t == 0){
        float inv = 1.f / (float)M_EDGES;
        float mu = ss[0]*inv;
        float var = sq[0]*inv - mu*mu;
        float sc = g1[c]*rsqrtf(var + 1e-5f);
        g_bn1[c] = sc;
        g_bn1[72 + c] = b1[c] - mu*sc;
    }
}

// ---------------- K4: main edge kernel (register-tiled matmuls) ----------------
// grid = 1024 (32 batches x 32 chunks of 512 edges), block = 256.
// Per 128-edge subtile: Z phase (z1->BN->relu), M1 (We2), gate, M2 (Wx1), gx, drain.
// M phases: thread tile = 4 edges x 9 outputs, edges packed in f32x2 lanes,
// weights pre-duplicated as u64 in SMEM (broadcast LDS.64).
__global__ void __launch_bounds__(256,1) k_edge(
    const float* __restrict__ x, const int* __restrict__ ei_all, const int* __restrict__ ej_all,
    const float* __restrict__ We1, const float* __restrict__ We2, const float* __restrict__ be2,
    const float* __restrict__ Wm, const float* __restrict__ bm,
    const float* __restrict__ Wx1, const float* __restrict__ bx1, const float* __restrict__ Wx2,
    float* __restrict__ out_m)
{
    extern __shared__ char smraw[];
    u64*   Ps    = (u64*)smraw;                  // 4608 u64
    u64*   Qs    = Ps + 4608;                    // 4608 u64
    u64*   We2d  = Qs + 4608;                    // 5184 u64 (dup'd)
    u64*   Wx1d  = We2d + 5184;                  // 5184 u64 (dup'd)
    float* s_act = (float*)(Wx1d + 5184);        // 72*132 floats
    float* xs    = s_act + 72*132;               // 640
    u64*   w144d = (u64*)(xs + 640);             // 36 (channel-paired, raw)
    u64*   w145d = w144d + 36;                   // 36
    float* sbn   = (float*)(w145d + 36);         // 144
    u64*   be2d  = (u64*)(sbn + 144);            // 72 (dup'd)
    u64*   bx1d  = be2d + 72;                    // 72 (dup'd)
    float* sWm   = (float*)(bx1d + 72);          // 72
    float* sWx2  = sWm + 72;                     // 72
    float* sgate = sWx2 + 72;                    // 8*132
    float* ssg   = sgate + 8*132;                // 128

    int tid = threadIdx.x;
    int b = blockIdx.x >> 5, chunk = blockIdx.x & 31;

    // ---- load phase ----
    const u64* Pg = (const u64*)g_P + (size_t)b*Nn*NP;
    const u64* Qg = (const u64*)g_Q + (size_t)b*Nn*NP;
    for (int t = tid; t < Nn*NP; t += 256){
        int i = t / NP, p = t - i*NP;
        Ps[p*Nn + i] = Pg[t];
        Qs[p*Nn + i] = Qg[t];
    }
    for (int t = tid; t < 5184; t += 256){
        We2d[t] = dup2(We2[t]);
        Wx1d[t] = dup2(Wx1[t]);
    }
    for (int t = tid; t < 512; t += 256) xs[(t>>2)*5 + (t&3)] = x[b*512 + t];
    for (int t = tid; t < 36; t += 256){
        w144d[t] = ((const u64*)(We1 + 144*72))[t];
        w145d[t] = ((const u64*)(We1 + 145*72))[t];
    }
    for (int t = tid; t < 144; t += 256) sbn[t] = g_bn1[t];
    for (int t = tid; t < 72; t += 256){
        be2d[t] = dup2(be2[t]);
        bx1d[t] = dup2(bx1[t]);
        sWm[t] = Wm[t];
        sWx2[t] = Wx2[t];
    }
    float bm0 = bm[0];

    int e128  = tid & 127;          // Z phase: edge in subtile
    int halfp = (tid >> 7) * 18;    // Z phase: p range base
    int eg = tid & 31;              // M phase: edge group (4 edges)
    int og = tid >> 5;              // M phase: out group (9 outs)
    int ebase = eg*4;
    int obase = og*9;

    for (int sub = 0; sub < 4; sub++){
        __syncthreads();   // prior drain / next Z hazard

        int geb = (b<<14) + (chunk<<9) + (sub<<7);

        // ---- Z: z1 -> BN1 -> relu -> s_act[k][e] ----
        {
            int ge = geb + e128;
            int i = ei_all[ge], j = ej_all[ge];
            float xi0=xs[i*5],xi1=xs[i*5+1],xi2=xs[i*5+2],xi3=xs[i*5+3];
            float xj0=xs[j*5],xj1=xs[j*5+1],xj2=xs[j*5+2],xj3=xs[j*5+3];
            float d0=xi0-xj0,d1=xi1-xj1,d2=xi2-xj2,d3=xi3-xj3;
            u64 dn = dup2(psi_f(d0*d0 - d1*d1 - d2*d2 - d3*d3));
            u64 dd = dup2(psi_f(xi0*xj0 - xi1*xj1 - xi2*xj2 - xi3*xj3));
#pragma unroll
            for (int pp = 0; pp < 18; pp++){
                int p = halfp + pp;
                u64 z = fadd2(Ps[p*Nn + i], Qs[p*Nn + j]);
                z = ffma2(dn, w144d[p], z);
                z = ffma2(dd, w145d[p], z);
                float2 v = unpack2(z);
                s_act[(2*p)*132 + e128]   = fmaxf(fmaf(v.x, sbn[2*p],   sbn[72+2*p]),   0.f);
                s_act[(2*p+1)*132 + e128] = fmaxf(fmaf(v.y, sbn[2*p+1], sbn[72+2*p+1]), 0.f);
            }
        }
        __syncthreads();

        // ---- M1: z2 = act @ We2 + be2 ----
        u64 acc0[9], acc1[9];
#pragma unroll
        for (int i = 0; i < 9; i++){ acc0[i] = be2d[obase+i]; acc1[i] = acc0[i]; }
        {
            const u64* W = We2d + obase;
#pragma unroll 4
            for (int k = 0; k < 72; k++){
                float4 a = *(const float4*)(s_act + k*132 + ebase);
                u64 u01 = pack2(a.x, a.y), u23 = pack2(a.z, a.w);
                const u64* Wk = W + k*72;
#pragma unroll
                for (int i = 0; i < 9; i++){
                    u64 w = Wk[i];
                    acc0[i] = ffma2(u01, w, acc0[i]);
                    acc1[i] = ffma2(u23, w, acc1[i]);
                }
            }
        }
        // relu + gate partials
        {
            float gp0=0.f, gp1=0.f, gp2=0.f, gp3=0.f;
#pragma unroll
            for (int i = 0; i < 9; i++){
                float wm = sWm[obase+i];
                float2 v0 = unpack2(acc0[i]); float2 v1 = unpack2(acc1[i]);
                float m00=fmaxf(v0.x,0.f), m01=fmaxf(v0.y,0.f);
                float m10=fmaxf(v1.x,0.f), m11=fmaxf(v1.y,0.f);
                gp0 = fmaf(m00, wm, gp0); gp1 = fmaf(m01, wm, gp1);
                gp2 = fmaf(m10, wm, gp2); gp3 = fmaf(m11, wm, gp3);
                acc0[i] = pack2(m00, m01); acc1[i] = pack2(m10, m11);
            }
            sgate[og*132 + ebase]   = gp0;
            sgate[og*132 + ebase+1] = gp1;
            sgate[og*132 + ebase+2] = gp2;
            sgate[og*132 + ebase+3] = gp3;
        }
        __syncthreads();
        if (og == 0){
#pragma unroll
            for (int q = 0; q < 4; q++){
                int e = ebase + q;
                float t = bm0;
#pragma unroll
                for (int g = 0; g < 8; g++) t += sgate[g*132 + e];
                ssg[e] = 1.f / (1.f + __expf(-t));
            }
        }
        __syncthreads();

        // ---- m = relu(z2)*sigmoid -> s_act[o][e] ----
        {
            u64 sg01 = pack2(ssg[ebase],   ssg[ebase+1]);
            u64 sg23 = pack2(ssg[ebase+2], ssg[ebase+3]);
#pragma unroll
            for (int i = 0; i < 9; i++){
                acc0[i] = mul2(acc0[i], sg01);
                acc1[i] = mul2(acc1[i], sg23);
                float2 v0 = unpack2(acc0[i]); float2 v1 = unpack2(acc1[i]);
                float4 st = make_float4(v0.x, v0.y, v1.x, v1.y);
                *(float4*)(s_act + (obase+i)*132 + ebase) = st;
            }
        }
        __syncthreads();

        // ---- M2: w = m @ Wx1 + bx1 ----
#pragma unroll
        for (int i = 0; i < 9; i++){ acc0[i] = bx1d[obase+i]; acc1[i] = acc0[i]; }
        {
            const u64* W = Wx1d + obase;
#pragma unroll 4
            for (int k = 0; k < 72; k++){
                float4 a = *(const float4*)(s_act + k*132 + ebase);
                u64 u01 = pack2(a.x, a.y), u23 = pack2(a.z, a.w);
                const u64* Wk = W + k*72;
#pragma unroll
                for (int i = 0; i < 9; i++){
                    u64 w = Wk[i];
                    acc0[i] = ffma2(u01, w, acc0[i]);
                    acc1[i] = ffma2(u23, w, acc1[i]);
                }
            }
        }
        // gx partials
        {
            float gp0=0.f, gp1=0.f, gp2=0.f, gp3=0.f;
#pragma unroll
            for (int i = 0; i < 9; i++){
                float wx = sWx2[obase+i];
                float2 v0 = unpack2(acc0[i]); float2 v1 = unpack2(acc1[i]);
                gp0 = fmaf(fmaxf(v0.x,0.f), wx, gp0);
                gp1 = fmaf(fmaxf(v0.y,0.f), wx, gp1);
                gp2 = fmaf(fmaxf(v1.x,0.f), wx, gp2);
                gp3 = fmaf(fmaxf(v1.y,0.f), wx, gp3);
            }
            sgate[og*132 + ebase]   = gp0;
            sgate[og*132 + ebase+1] = gp1;
            sgate[og*132 + ebase+2] = gp2;
            sgate[og*132 + ebase+3] = gp3;
        }
        __syncthreads();
        if (og == 0){
#pragma unroll
            for (int q = 0; q < 4; q++){
                int e = ebase + q;
                float t = 0.f;
#pragma unroll
                for (int g = 0; g < 8; g++) t += sgate[g*132 + e];
                g_gx[geb + e] = t;
            }
        }

        // ---- drain m (coalesced) ----
        {
            float* dst = out_m + (size_t)geb*72;
            for (int t = tid; t < 128*72; t += 256){
                int e = t / 72, o = t - e*72;
                dst[t] = s_act[o*132 + e];
            }
        }
    }
}

// ---------------- K5: segment partials (SMEM-staged ballot scan) ---------------
// grid = 2048: (b, node-group of 8, quarter-chunk of 4096 edges). block = 256.
__global__ void __launch_bounds__(256) k_agg(const float* __restrict__ x,
                                             const int* __restrict__ ei_all,
                                             const int* __restrict__ ej_all,
                                             const float* __restrict__ out_m){
    __shared__ int sei[4096];
    __shared__ int sej[4096];
    __shared__ float xs[512];
    int tid = threadIdx.x;
    int b = blockIdx.x >> 6;
    int r = blockIdx.x & 63;
    int ng = r >> 2, cq = r & 3;
    int ebase = b*Ee + cq*4096;
    for (int t = tid; t < 4096; t += 256){
        sei[t] = ei_all[ebase + t];
        sej[t] = ej_all[ebase + t];
    }
    for (int t = tid; t < 512; t += 256) xs[t] = x[b*512 + t];
    __syncthreads();

    int wid = tid >> 5, lane = tid & 31;
    int node = ng*8 + wid;
    float xi0=xs[node*4], xi1=xs[node*4+1], xi2=xs[node*4+2], xi3=xs[node*4+3];

    float m0=0.f, m1=0.f, m2=0.f;
    float xa0=0.f, xa1=0.f, xa2=0.f, xa3=0.f;
    int cnt = 0;

    for (int base = 0; base < 4096; base += 32){
        unsigned msk = __ballot_sync(0xffffffffu, sei[base + lane] == node);
        cnt += __popc(msk);
        while (msk){
            int bit = __ffs(msk) - 1; msk &= msk - 1;
            int el = base + bit;
            const float* mr = out_m + (size_t)(ebase + el)*72;
            m0 += mr[lane];
            m1 += mr[32 + lane];
            if (lane < 8) m2 += mr[64 + lane];
            float g = g_gx[ebase + el];
            int j = sej[el];
            xa0 += fminf(fmaxf((xi0 - xs[j*4+0])*g, -100.f), 100.f);
            xa1 += fminf(fmaxf((xi1 - xs[j*4+1])*g, -100.f), 100.f);
            xa2 += fminf(fmaxf((xi2 - xs[j*4+2])*g, -100.f), 100.f);
            xa3 += fminf(fmaxf((xi3 - xs[j*4+3])*g, -100.f), 100.f);
        }
    }
    float* P = g_aggp + ((size_t)(b*Nn + node)*4 + cq)*80;
    P[lane] = m0;
    P[32 + lane] = m1;
    if (lane < 8) P[64 + lane] = m2;
    if (lane == 0){
        P[72] = xa0; P[73] = xa1; P[74] = xa2; P[75] = xa3;
        P[76] = (float)cnt;
    }
}

// ---------------- K5b: combine partials (deterministic fixed order) ------------
__global__ void __launch_bounds__(256) k_agg2(const float* __restrict__ x,
                                              float* __restrict__ out_x){
    int nid = blockIdx.x*8 + (threadIdx.x >> 5);
    int lane = threadIdx.x & 31;
    const float* P = g_aggp + (size_t)nid*320;
    float m0 = P[lane]     + P[80+lane]     + P[160+lane]     + P[240+lane];
    float m1 = P[32+lane]  + P[112+lane]    + P[192+lane]     + P[272+lane];
    float* mg = g_magg + (size_t)nid*72;
    mg[lane] = m0;
    mg[32 + lane] = m1;
    if (lane < 8){
        float m2 = P[64+lane] + P[144+lane] + P[224+lane] + P[304+lane];
        mg[64 + lane] = m2;
    }
    if (lane < 4){
        float xa  = P[72+lane] + P[152+lane] + P[232+lane] + P[312+lane];
        float cnt = P[76]      + P[156]      + P[236]      + P[316];
        out_x[(size_t)nid*4 + lane] = x[(size_t)nid*4 + lane] + xa / fmaxf(cnt, 1.f);
    }
}

// ---------------- K6: z2pre = [h, magg, attr] @ Wh1 + bh1; BN2 partials --------
__global__ void __launch_bounds__(256) k_stats2(const float* __restrict__ h,
                                                const float* __restrict__ na,
                                                const float* __restrict__ Wh1,
                                                const float* __restrict__ bh1){
    __shared__ float sW[148*72];
    for (int t = threadIdx.x; t < 148*72; t += 256) sW[t] = Wh1[t];
    __syncthreads();
    int node = blockIdx.x*256 + threadIdx.x;
    const u64* Wu = (const u64*)sW;
    const u64* bu = (const u64*)bh1;
    u64 acc[NP];
#pragma unroll
    for (int p = 0; p < NP; p++) acc[p] = bu[p];
    const float* hr = h + (size_t)node*72;
#pragma unroll 4
    for (int k = 0; k < 72; k++){
        u64 f = dup2(hr[k]);
        const u64* row = Wu + k*NP;
#pragma unroll
        for (int p = 0; p < NP; p++) acc[p] = ffma2(f, row[p], acc[p]);
    }
    const float* mr = g_magg + (size_t)node*72;
#pragma unroll 4
    for (int k = 0; k < 72; k++){
        u64 f = dup2(mr[k]);
        const u64* row = Wu + (72 + k)*NP;
#pragma unroll
        for (int p = 0; p < NP; p++) acc[p] = ffma2(f, row[p], acc[p]);
    }
    const float* ar = na + (size_t)node*4;
#pragma unroll
    for (int k = 0; k < 4; k++){
        u64 f = dup2(ar[k]);
        const u64* row = Wu + (144 + k)*NP;
#pragma unroll
        for (int p = 0; p < NP; p++) acc[p] = ffma2(f, row[p], acc[p]);
    }
    u64* zo = (u64*)(g_z2 + (size_t)node*72);
#pragma unroll
    for (int p = 0; p < NP; p++) zo[p] = acc[p];

    int lane = threadIdx.x & 31, wid = threadIdx.x >> 5;
    int gw = blockIdx.x*8 + wid;
#pragma unroll
    for (int p = 0; p < NP; p++){
        float2 v = unpack2(acc[p]);
        float s0 = wred(v.x), s1 = wred(v.y);
        float q0 = wred(v.x*v.x), q1 = wred(v.y*v.y);
        if (lane == 0){
            g_part2s[(2*p)*128 + gw] = s0; g_part2s[(2*p+1)*128 + gw] = s1;
            g_part2q[(2*p)*128 + gw] = q0; g_part2q[(2*p+1)*128 + gw] = q1;
        }
    }
}

// ---------------- K7: finalize BN2 ---------------------------------------------
__global__ void k_red2(const float* __restrict__ gh, const float* __restrict__ bh){
    __shared__ float ss[128], sq[128];
    int c = blockIdx.x, t = threadIdx.x;
    ss[t] = g_part2s[c*128 + t];
    sq[t] = g_part2q[c*128 + t];
    __syncthreads();
    for (int o = 64; o; o >>= 1){
        if (t < o){ ss[t] += ss[t+o]; sq[t] += sq[t+o]; }
        __syncthreads();
    }
    if (t == 0){
        float inv = 1.f/4096.f;
        float mu = ss[0]*inv;
        float var = sq[0]*inv - mu*mu;
        float sc = gh[c]*rsqrtf(var + 1e-5f);
        g_bn2[c] = sc;
        g_bn2[72 + c] = bh[c] - mu*sc;
    }
}

// ---------------- K8: h_out -----------------------------------------------------
__global__ void __launch_bounds__(256) k_h(const float* __restrict__ h,
                                           const float* __restrict__ Wh2,
                                           const float* __restrict__ bh2,
                                           float* __restrict__ out_h){
    extern __shared__ char smraw[];
    float* sW   = (float*)smraw;   // 5184
    float* sbn  = sW + 5184;       // 144
    float* sb2  = sbn + 144;       // 72
    float* s_act= sb2 + 72;        // 72*257
    int tid = threadIdx.x;
    for (int t = tid; t < 5184; t += 256) sW[t] = Wh2[t];
    for (int t = tid; t < 144; t += 256) sbn[t] = g_bn2[t];
    for (int t = tid; t < 72; t += 256) sb2[t] = bh2[t];
    __syncthreads();
    int node = blockIdx.x*256 + tid;
    const float* zr = g_z2 + (size_t)node*72;
#pragma unroll 4
    for (int c = 0; c < 72; c++)
        s_act[c*257 + tid] = fmaxf(fmaf(zr[c], sbn[c], sbn[72+c]), 0.f);
    const u64* Wu = (const u64*)sW;
    const u64* bu = (const u64*)sb2;
    u64 acc[NP];
#pragma unroll
    for (int p = 0; p < NP; p++) acc[p] = bu[p];
#pragma unroll 4
    for (int k = 0; k < 72; k++){
        u64 f = dup2(s_act[k*257 + tid]);
        const u64* row = Wu + k*NP;
#pragma unroll
        for (int p = 0; p < NP; p++) acc[p] = ffma2(f, row[p], acc[p]);
    }
    const float* hr = h + (size_t)node*72;
    float* o = out_h + (size_t)node*72;
#pragma unroll
    for (int p = 0; p < NP; p++){
        float2 v = unpack2(acc[p]);
        o[2*p]   = hr[2*p]   + v.x;
        o[2*p+1] = hr[2*p+1] + v.y;
    }
}

// ---------------- launch ---------------------------------------------------------
#define SMEM_STATS1 81472
// Ps 36864 + Qs 36864 + We2d 41472 + Wx1d 41472 + s_act 38016 + xs 2560
// + w144d/w145d 576 + sbn 576 + be2d/bx1d 1152 + sWm/sWx2 576 + sgate 4224 + ssg 512
#define SMEM_EDGE   204864
#define SMEM_H      95616

extern "C" void kernel_launch(void* const* d_in, const int* in_sizes, int n_in,
                              void* d_out, int out_size){
    const float* h   = (const float*)d_in[0];
    const float* x   = (const float*)d_in[1];
    const int*   ei  = (const int*)d_in[2];
    const int*   ej  = (const int*)d_in[3];
    const float* na  = (const float*)d_in[4];
    const float* We1 = (const float*)d_in[5];
    const float* g1  = (const float*)d_in[6];
    const float* b1  = (const float*)d_in[7];
    const float* We2 = (const float*)d_in[8];
    const float* be2 = (const float*)d_in[9];
    const float* Wm  = (const float*)d_in[10];
    const float* bm  = (const float*)d_in[11];
    const float* Wx1 = (const float*)d_in[12];
    const float* bx1 = (const float*)d_in[13];
    const float* Wx2 = (const float*)d_in[14];
    const float* Wh1 = (const float*)d_in[15];
    const float* bh1 = (const float*)d_in[16];
    const float* gh  = (const float*)d_in[17];
    const float* bh  = (const float*)d_in[18];
    const float* Wh2 = (const float*)d_in[19];
    const float* bh2 = (const float*)d_in[20];

    float* out   = (float*)d_out;
    float* out_h = out;                 // [B,N,72]
    float* out_x = out + 294912;        // [B,N,4]
    float* out_m = out + 311296;        // [B,E,72]

    cudaFuncSetAttribute(k_stats1, cudaFuncAttributeMaxDynamicSharedMemorySize, SMEM_STATS1);
    cudaFuncSetAttribute(k_edge,   cudaFuncAttributeMaxDynamicSharedMemorySize, SMEM_EDGE);
    cudaFuncSetAttribute(k_h,      cudaFuncAttributeMaxDynamicSharedMemorySize, SMEM_H);

    k_pq    <<<16, 256>>>(h, We1);
    k_stats1<<<512, 256, SMEM_STATS1>>>(x, ei, ej, We1);
    k_red1  <<<72, 256>>>(g1, b1);
    k_edge  <<<1024, 256, SMEM_EDGE>>>(x, ei, ej, We1, We2, be2, Wm, bm, Wx1, bx1, Wx2, out_m);
    k_agg   <<<2048, 256>>>(x, ei, ej, out_m);
    k_agg2  <<<512, 256>>>(x, out_x);
    k_stats2<<<16, 256>>>(h, na, Wh1, bh1);
    k_red2  <<<72, 128>>>(gh, bh);
    k_h     <<<16, 256, SMEM_H>>>(h, Wh2, bh2, out_h);
}

// round 4
// speedup vs baseline: 1.3661x; 1.1503x over previous
#include <cuda_runtime.h>
#include <cuda_bf16.h>
#include <cstdint>
#include <math.h>

#define Bz 32
#define Nn 128
#define Ee 16384
#define NP 36
#define M_EDGES (Bz*Ee)   /* 524288 */
#define M_NODES (Bz*Nn)   /* 4096   */

typedef unsigned long long u64;

// ---------------- scratch (static device globals; no runtime allocs) ---------
__device__ float g_P[M_NODES*72];
__device__ float g_Q[M_NODES*72];
__device__ float g_gx[M_EDGES];
__device__ float g_magg[M_NODES*72];
__device__ float g_z2[M_NODES*72];
__device__ float g_part1s[72*512];
__device__ float g_part1q[72*512];
__device__ float g_part2s[72*128];
__device__ float g_part2q[72*128];
__device__ float g_bn1[144];
__device__ float g_bn2[144];
__device__ float g_aggp[M_NODES*4*80];   // per (node, quarter-chunk) partials

// ---------------- packed fp32x2 helpers (Blackwell) ---------------------------
__device__ __forceinline__ u64 ffma2(u64 a, u64 b, u64 c){
    u64 d; asm("fma.rn.f32x2 %0,%1,%2,%3;" : "=l"(d) : "l"(a), "l"(b), "l"(c)); return d;
}
__device__ __forceinline__ u64 fadd2(u64 a, u64 b){
    u64 d; asm("add.rn.f32x2 %0,%1,%2;" : "=l"(d) : "l"(a), "l"(b)); return d;
}
__device__ __forceinline__ u64 mul2(u64 a, u64 b){
    u64 d; asm("mul.rn.f32x2 %0,%1,%2;" : "=l"(d) : "l"(a), "l"(b)); return d;
}
__device__ __forceinline__ u64 dup2(float x){
    u64 d; unsigned r = __float_as_uint(x);
    asm("mov.b64 %0,{%1,%1};" : "=l"(d) : "r"(r)); return d;
}
__device__ __forceinline__ u64 pack2(float a, float b){
    u64 d; asm("mov.b64 %0,{%1,%2};" : "=l"(d) : "r"(__float_as_uint(a)), "r"(__float_as_uint(b))); return d;
}
__device__ __forceinline__ float2 unpack2(u64 v){
    unsigned lo, hi; asm("mov.b64 {%0,%1},%2;" : "=r"(lo), "=r"(hi) : "l"(v));
    return make_float2(__uint_as_float(lo), __uint_as_float(hi));
}
__device__ __forceinline__ float psi_f(float p){
    return copysignf(log1pf(fabsf(p)), p);
}
__device__ __forceinline__ float wred(float v){
#pragma unroll
    for (int o = 16; o; o >>= 1) v += __shfl_xor_sync(0xffffffffu, v, o);
    return v;
}
__device__ __forceinline__ float clamp100(float v){
    return fminf(fmaxf(v, -100.f), 100.f);
}

// ---------------- K1: P = h @ We1[0:72], Q = h @ We1[72:144] -------------------
__global__ void __launch_bounds__(256) k_pq(const float* __restrict__ h,
                                            const float* __restrict__ We1){
    __shared__ float sW[144*72];
    for (int t = threadIdx.x; t < 144*72; t += 256) sW[t] = We1[t];
    __syncthreads();
    int node = blockIdx.x*256 + threadIdx.x;
    const u64* Wu = (const u64*)sW;
    const float* hr = h + (size_t)node*72;
    u64 acc[NP];
#pragma unroll
    for (int p = 0; p < NP; p++) acc[p] = 0ull;
#pragma unroll 4
    for (int k = 0; k < 72; k++){
        u64 f = dup2(hr[k]);
        const u64* row = Wu + k*NP;
#pragma unroll
        for (int p = 0; p < NP; p++) acc[p] = ffma2(f, row[p], acc[p]);
    }
    u64* o = (u64*)(g_P + (size_t)node*72);
#pragma unroll
    for (int p = 0; p < NP; p++) o[p] = acc[p];
#pragma unroll
    for (int p = 0; p < NP; p++) acc[p] = 0ull;
#pragma unroll 4
    for (int k = 0; k < 72; k++){
        u64 f = dup2(hr[k]);
        const u64* row = Wu + (72 + k)*NP;
#pragma unroll
        for (int p = 0; p < NP; p++) acc[p] = ffma2(f, row[p], acc[p]);
    }
    o = (u64*)(g_Q + (size_t)node*72);
#pragma unroll
    for (int p = 0; p < NP; p++) o[p] = acc[p];
}

// ---------------- K2: BN1 statistics (per-block partials, deterministic) ------
__global__ void __launch_bounds__(256) k_stats1(const float* __restrict__ x,
                                                const int* __restrict__ ei_all,
                                                const int* __restrict__ ej_all,
                                                const float* __restrict__ We1){
    extern __shared__ char smraw[];
    u64*   Ps   = (u64*)smraw;          // 4608 u64
    u64*   Qs   = Ps + 4608;            // 4608 u64
    float* xs   = (float*)(Qs + 4608);  // 640
    float* w144 = xs + 640;             // 72
    float* w145 = w144 + 72;            // 72
    float* sred = w145 + 72;            // 576
    float* sredq= sred + 576;           // 576

    int tid = threadIdx.x;
    int b = blockIdx.x >> 4, chunk = blockIdx.x & 15;

    const u64* Pg = (const u64*)g_P + (size_t)b*Nn*NP;
    const u64* Qg = (const u64*)g_Q + (size_t)b*Nn*NP;
    for (int t = tid; t < Nn*NP; t += 256){
        int i = t / NP, p = t - i*NP;
        Ps[p*Nn + i] = Pg[t];
        Qs[p*Nn + i] = Qg[t];
    }
    for (int t = tid; t < 512; t += 256) xs[(t>>2)*5 + (t&3)] = x[b*512 + t];
    for (int t = tid; t < 72; t += 256){
        w144[t] = We1[144*72 + t];
        w145[t] = We1[145*72 + t];
    }
    __syncthreads();
    const u64* w144u = (const u64*)w144;
    const u64* w145u = (const u64*)w145;

    u64 sum[NP], ssq[NP];
#pragma unroll
    for (int p = 0; p < NP; p++){ sum[p] = 0ull; ssq[p] = 0ull; }

    for (int it = 0; it < 4; it++){
        int ge = (b<<14) + (chunk<<10) + (it<<8) + tid;
        int i = ei_all[ge], j = ej_all[ge];
        float xi0=xs[i*5],xi1=xs[i*5+1],xi2=xs[i*5+2],xi3=xs[i*5+3];
        float xj0=xs[j*5],xj1=xs[j*5+1],xj2=xs[j*5+2],xj3=xs[j*5+3];
        float d0=xi0-xj0,d1=xi1-xj1,d2=xi2-xj2,d3=xi3-xj3;
        u64 dn = dup2(psi_f(d0*d0 - d1*d1 - d2*d2 - d3*d3));
        u64 dd = dup2(psi_f(xi0*xj0 - xi1*xj1 - xi2*xj2 - xi3*xj3));
#pragma unroll
        for (int p = 0; p < NP; p++){
            u64 z = fadd2(Ps[p*Nn + i], Qs[p*Nn + j]);
            z = ffma2(dn, w144u[p], z);
            z = ffma2(dd, w145u[p], z);
            sum[p] = fadd2(sum[p], z);
            ssq[p] = ffma2(z, z, ssq[p]);
        }
    }
    int lane = tid & 31, wid = tid >> 5;
#pragma unroll
    for (int p = 0; p < NP; p++){
        float2 s = unpack2(sum[p]), q = unpack2(ssq[p]);
        float s0 = wred(s.x), s1 = wred(s.y), q0 = wred(q.x), q1 = wred(q.y);
        if (lane == 0){
            sred [wid*72 + 2*p]   = s0; sred [wid*72 + 2*p+1] = s1;
            sredq[wid*72 + 2*p]   = q0; sredq[wid*72 + 2*p+1] = q1;
        }
    }
    __syncthreads();
    if (tid < 72){
        float S = 0.f, Q = 0.f;
        for (int w = 0; w < 8; w++){ S += sred[w*72 + tid]; Q += sredq[w*72 + tid]; }
        g_part1s[tid*512 + blockIdx.x] = S;
        g_part1q[tid*512 + blockIdx.x] = Q;
    }
}

// ---------------- K3: finalize BN1 ---------------------------------------------
__global__ void k_red1(const float* __restrict__ g1, const float* __restrict__ b1){
    __shared__ float ss[256], sq[256];
    int c = blockIdx.x, t = threadIdx.x;
    ss[t] = g_part1s[c*512 + t] + g_part1s[c*512 + 256 + t];
    sq[t] = g_part1q[c*512 + t] + g_part1q[c*512 + 256 + t];
    __syncthreads();
    for (int o = 128; o; o >>= 1){
        if (t < o){ ss[t] += ss[t+o]; sq[t] += sq[t+o]; }
        __syncthreads();
    }
    if (t == 0){
        float inv = 1.f / (float)M_EDGES;
        float mu = ss[0]*inv;
        float var = sq[0]*inv - mu*mu;
        float sc = g1[c]*rsqrtf(var + 1e-5f);
        g_bn1[c] = sc;
        g_bn1[72 + c] = b1[c] - mu*sc;
    }
}

// ---------------- K4: main edge kernel (output-packed tiles, 2 CTAs/SM) --------
// grid = 2048 (32 b x 64 chunks of 256 edges), block = 256, 2 subtiles of 128.
// M phases: thread = 2 edges x 18 outs; acc u64 packs an OUTPUT pair, so weights
// load as natural u64 pairs (broadcast LDS.128/64, no duplication). Z phase
// reads P/Q rows from gmem (L2-resident), killing the random-index smem gather.
__global__ void __launch_bounds__(256,2) k_edge(
    const float* __restrict__ x, const int* __restrict__ ei_all, const int* __restrict__ ej_all,
    const float* __restrict__ We1, const float* __restrict__ We2, const float* __restrict__ be2,
    const float* __restrict__ Wm, const float* __restrict__ bm,
    const float* __restrict__ Wx1, const float* __restrict__ bx1, const float* __restrict__ Wx2,
    float* __restrict__ out_m)
{
    extern __shared__ char smraw[];
    u64*   sW2u  = (u64*)smraw;                // [4 og][72 k][10] u64 (9 used + pad)
    u64*   sW1u  = sW2u + 2880;                // 2880 u64
    u64*   w144p = sW1u + 2880;                // 36
    u64*   w145p = w144p + 36;                 // 36
    u64*   be2u  = w145p + 36;                 // 36
    u64*   bx1u  = be2u + 36;                  // 36
    float* s_act = (float*)(bx1u + 36);        // 72*130
    float* xs    = s_act + 72*130;             // 640
    float* sbn   = xs + 640;                   // 144
    float* sWm   = sbn + 144;                  // 72
    float* sWx2  = sWm + 72;                   // 72
    float* sgate = sWx2 + 72;                  // 4*132
    float* ssg   = sgate + 4*132;              // 128

    int tid = threadIdx.x;
    int b = blockIdx.x >> 6, c64 = blockIdx.x & 63;

    // ---- stage weights (rearranged per-og, 16B aligned) ----
    for (int t = tid; t < 5184; t += 256){
        int k = t / 72, o = t - k*72;
        int og = o / 18, local = o - og*18;
        int fi = ((og*72 + k)*10 + (local >> 1))*2 + (local & 1);
        ((float*)sW2u)[fi] = We2[t];
        ((float*)sW1u)[fi] = Wx1[t];
    }
    for (int t = tid; t < 36; t += 256){
        w144p[t] = ((const u64*)(We1 + 144*72))[t];
        w145p[t] = ((const u64*)(We1 + 145*72))[t];
        be2u[t]  = ((const u64*)be2)[t];
        bx1u[t]  = ((const u64*)bx1)[t];
    }
    for (int t = tid; t < 512; t += 256) xs[(t>>2)*5 + (t&3)] = x[b*512 + t];
    for (int t = tid; t < 144; t += 256) sbn[t] = g_bn1[t];
    for (int t = tid; t < 72; t += 256){ sWm[t] = Wm[t]; sWx2[t] = Wx2[t]; }
    float bm0 = bm[0];

    int e128 = tid & 127, half = tid >> 7;     // Z phase roles
    int og = tid >> 6, eg = tid & 63;          // M phase roles
    int obase = og*18;
    const u64* PuB = (const u64*)g_P + (size_t)(b*Nn)*36;
    const u64* QuB = (const u64*)g_Q + (size_t)(b*Nn)*36;

    for (int sub = 0; sub < 2; sub++){
        __syncthreads();   // staging / prior drain barrier
        int geb = (b<<14) + (c64<<8) + (sub<<7);

        // ---- Z: z1 -> BN1 -> relu -> s_act[k][e] (P/Q from L2) ----
        {
            int ge = geb + e128;
            int i = ei_all[ge], j = ej_all[ge];
            float xi0=xs[i*5],xi1=xs[i*5+1],xi2=xs[i*5+2],xi3=xs[i*5+3];
            float xj0=xs[j*5],xj1=xs[j*5+1],xj2=xs[j*5+2],xj3=xs[j*5+3];
            float d0=xi0-xj0,d1=xi1-xj1,d2=xi2-xj2,d3=xi3-xj3;
            u64 dn = dup2(psi_f(d0*d0 - d1*d1 - d2*d2 - d3*d3));
            u64 dd = dup2(psi_f(xi0*xj0 - xi1*xj1 - xi2*xj2 - xi3*xj3));
            const u64* Pu = PuB + (size_t)i*36;
            const u64* Qu = QuB + (size_t)j*36;
#pragma unroll 6
            for (int pp = 0; pp < 18; pp++){
                int p = half*18 + pp;
                u64 z = fadd2(Pu[p], Qu[p]);
                z = ffma2(dn, w144p[p], z);
                z = ffma2(dd, w145p[p], z);
                float2 v = unpack2(z);
                s_act[(2*p)*130   + e128] = fmaxf(fmaf(v.x, sbn[2*p],   sbn[72+2*p]),   0.f);
                s_act[(2*p+1)*130 + e128] = fmaxf(fmaf(v.y, sbn[2*p+1], sbn[72+2*p+1]), 0.f);
            }
        }
        __syncthreads();

        u64 acc0[9], acc1[9];

        // ---- M1: z2 = act @ We2 + be2 (edges 2eg, 2eg+1; outs obase..obase+17)
#pragma unroll
        for (int i = 0; i < 9; i++){ acc0[i] = be2u[og*9 + i]; acc1[i] = acc0[i]; }
        {
            const u64* W = sW2u + (size_t)(og*72)*10;
#pragma unroll 2
            for (int k = 0; k < 72; k++){
                const u64* Wb = W + k*10;
                u64 w[9];
                { ulonglong2 t0 = *(const ulonglong2*)(Wb);
                  ulonglong2 t1 = *(const ulonglong2*)(Wb+2);
                  ulonglong2 t2 = *(const ulonglong2*)(Wb+4);
                  ulonglong2 t3 = *(const ulonglong2*)(Wb+6);
                  w[0]=t0.x; w[1]=t0.y; w[2]=t1.x; w[3]=t1.y;
                  w[4]=t2.x; w[5]=t2.y; w[6]=t3.x; w[7]=t3.y; w[8]=Wb[8]; }
                float2 a = *(const float2*)(s_act + k*130 + 2*eg);
                u64 a0 = dup2(a.x), a1 = dup2(a.y);
#pragma unroll
                for (int i = 0; i < 9; i++){
                    acc0[i] = ffma2(a0, w[i], acc0[i]);
                    acc1[i] = ffma2(a1, w[i], acc1[i]);
                }
            }
        }
        // relu + gate partials
        {
            float gp0 = 0.f, gp1 = 0.f;
#pragma unroll
            for (int i = 0; i < 9; i++){
                float wm0 = sWm[obase + 2*i], wm1 = sWm[obase + 2*i + 1];
                float2 v0 = unpack2(acc0[i]); float2 v1 = unpack2(acc1[i]);
                float m00=fmaxf(v0.x,0.f), m01=fmaxf(v0.y,0.f);
                float m10=fmaxf(v1.x,0.f), m11=fmaxf(v1.y,0.f);
                gp0 = fmaf(m00, wm0, fmaf(m01, wm1, gp0));
                gp1 = fmaf(m10, wm0, fmaf(m11, wm1, gp1));
                acc0[i] = pack2(m00, m01); acc1[i] = pack2(m10, m11);
            }
            *(float2*)(sgate + og*132 + 2*eg) = make_float2(gp0, gp1);
        }
        __syncthreads();
        if (tid < 128){
            float t = bm0 + sgate[tid] + sgate[132+tid] + sgate[264+tid] + sgate[396+tid];
            ssg[tid] = 1.f / (1.f + __expf(-t));
        }
        __syncthreads();

        // ---- m = relu(z2)*sigmoid -> s_act[o][e] (overwrites act) ----
        {
            u64 s0 = dup2(ssg[2*eg]), s1 = dup2(ssg[2*eg + 1]);
#pragma unroll
            for (int i = 0; i < 9; i++){
                acc0[i] = mul2(acc0[i], s0);
                acc1[i] = mul2(acc1[i], s1);
                float2 v0 = unpack2(acc0[i]); float2 v1 = unpack2(acc1[i]);
                *(float2*)(s_act + (obase+2*i)*130   + 2*eg) = make_float2(v0.x, v1.x);
                *(float2*)(s_act + (obase+2*i+1)*130 + 2*eg) = make_float2(v0.y, v1.y);
            }
        }
        __syncthreads();

        // ---- M2: w = m @ Wx1 + bx1 ----
#pragma unroll
        for (int i = 0; i < 9; i++){ acc0[i] = bx1u[og*9 + i]; acc1[i] = acc0[i]; }
        {
            const u64* W = sW1u + (size_t)(og*72)*10;
#pragma unroll 2
            for (int k = 0; k < 72; k++){
                const u64* Wb = W + k*10;
                u64 w[9];
                { ulonglong2 t0 = *(const ulonglong2*)(Wb);
                  ulonglong2 t1 = *(const ulonglong2*)(Wb+2);
                  ulonglong2 t2 = *(const ulonglong2*)(Wb+4);
                  ulonglong2 t3 = *(const ulonglong2*)(Wb+6);
                  w[0]=t0.x; w[1]=t0.y; w[2]=t1.x; w[3]=t1.y;
                  w[4]=t2.x; w[5]=t2.y; w[6]=t3.x; w[7]=t3.y; w[8]=Wb[8]; }
                float2 a = *(const float2*)(s_act + k*130 + 2*eg);
                u64 a0 = dup2(a.x), a1 = dup2(a.y);
#pragma unroll
                for (int i = 0; i < 9; i++){
                    acc0[i] = ffma2(a0, w[i], acc0[i]);
                    acc1[i] = ffma2(a1, w[i], acc1[i]);
                }
            }
        }
        // gx partials
        {
            float gp0 = 0.f, gp1 = 0.f;
#pragma unroll
            for (int i = 0; i < 9; i++){
                float wx0 = sWx2[obase + 2*i], wx1 = sWx2[obase + 2*i + 1];
                float2 v0 = unpack2(acc0[i]); float2 v1 = unpack2(acc1[i]);
                gp0 = fmaf(fmaxf(v0.x,0.f), wx0, fmaf(fmaxf(v0.y,0.f), wx1, gp0));
                gp1 = fmaf(fmaxf(v1.x,0.f), wx0, fmaf(fmaxf(v1.y,0.f), wx1, gp1));
            }
            *(float2*)(sgate + og*132 + 2*eg) = make_float2(gp0, gp1);
        }
        __syncthreads();
        if (tid < 128)
            g_gx[geb + tid] = sgate[tid] + sgate[132+tid] + sgate[264+tid] + sgate[396+tid];

        // ---- drain m (coalesced gmem, 2-way smem conflict) ----
        {
            float* dst = out_m + (size_t)geb*72;
            for (int t = tid; t < 128*72; t += 256){
                int e = t / 72, o = t - e*72;
                dst[t] = s_act[o*130 + e];
            }
        }
    }
}

// ---------------- K5: segment partials (match-list, MLP-4 processing) ----------
// grid = 2048: (b, node-group of 8, quarter-chunk of 4096 edges). block = 256.
__global__ void __launch_bounds__(256) k_agg(const float* __restrict__ x,
                                             const int* __restrict__ ei_all,
                                             const int* __restrict__ ej_all,
                                             const float* __restrict__ out_m){
    __shared__ int sei[4096];
    __shared__ int sej[4096];
    __shared__ float xs[512];
    __shared__ int slist[8][168];
    int tid = threadIdx.x;
    int b = blockIdx.x >> 6;
    int r = blockIdx.x & 63;
    int ng = r >> 2, cq = r & 3;
    int gbase = b*Ee + cq*4096;
    for (int t = tid; t < 4096; t += 256){
        sei[t] = ei_all[gbase + t];
        sej[t] = ej_all[gbase + t];
    }
    for (int t = tid; t < 512; t += 256) xs[t] = x[b*512 + t];
    __syncthreads();

    int wid = tid >> 5, lane = tid & 31;
    int node = ng*8 + wid;
    int* list = slist[wid];
    unsigned lmask = (1u << lane) - 1u;
    float xi0=xs[node*4], xi1=xs[node*4+1], xi2=xs[node*4+2], xi3=xs[node*4+3];

    float m0=0.f, m1=0.f, m2=0.f;
    float xa0=0.f, xa1=0.f, xa2=0.f, xa3=0.f;
    int cnt = 0, lc = 0;

    auto process = [&](int n){
        int q = 0;
        for (; q + 4 <= n; q += 4){
            int e0=list[q], e1=list[q+1], e2=list[q+2], e3=list[q+3];
            const float* r0 = out_m + (size_t)(gbase+e0)*72;
            const float* r1 = out_m + (size_t)(gbase+e1)*72;
            const float* r2 = out_m + (size_t)(gbase+e2)*72;
            const float* r3 = out_m + (size_t)(gbase+e3)*72;
            float a0=r0[lane], a1=r1[lane], a2=r2[lane], a3=r3[lane];
            float b0=r0[32+lane], b1=r1[32+lane], b2=r2[32+lane], b3=r3[32+lane];
            float c0=0.f,c1=0.f,c2=0.f,c3=0.f;
            if (lane < 8){ c0=r0[64+lane]; c1=r1[64+lane]; c2=r2[64+lane]; c3=r3[64+lane]; }
            float g0=g_gx[gbase+e0], g1=g_gx[gbase+e1], g2=g_gx[gbase+e2], g3=g_gx[gbase+e3];
            int j0=sej[e0], j1=sej[e1], j2=sej[e2], j3=sej[e3];
            m0 += a0; m0 += a1; m0 += a2; m0 += a3;
            m1 += b0; m1 += b1; m1 += b2; m1 += b3;
            m2 += c0; m2 += c1; m2 += c2; m2 += c3;
            xa0 += clamp100((xi0 - xs[j0*4+0])*g0); xa1 += clamp100((xi1 - xs[j0*4+1])*g0);
            xa2 += clamp100((xi2 - xs[j0*4+2])*g0); xa3 += clamp100((xi3 - xs[j0*4+3])*g0);
            xa0 += clamp100((xi0 - xs[j1*4+0])*g1); xa1 += clamp100((xi1 - xs[j1*4+1])*g1);
            xa2 += clamp100((xi2 - xs[j1*4+2])*g1); xa3 += clamp100((xi3 - xs[j1*4+3])*g1);
            xa0 += clamp100((xi0 - xs[j2*4+0])*g2); xa1 += clamp100((xi1 - xs[j2*4+1])*g2);
            xa2 += clamp100((xi2 - xs[j2*4+2])*g2); xa3 += clamp100((xi3 - xs[j2*4+3])*g2);
            xa0 += clamp100((xi0 - xs[j3*4+0])*g3); xa1 += clamp100((xi1 - xs[j3*4+1])*g3);
            xa2 += clamp100((xi2 - xs[j3*4+2])*g3); xa3 += clamp100((xi3 - xs[j3*4+3])*g3);
        }
        for (; q < n; q++){
            int e = list[q];
            const float* mr = out_m + (size_t)(gbase+e)*72;
            m0 += mr[lane];
            m1 += mr[32+lane];
            if (lane < 8) m2 += mr[64+lane];
            float g = g_gx[gbase+e];
            int j = sej[e];
            xa0 += clamp100((xi0 - xs[j*4+0])*g);
            xa1 += clamp100((xi1 - xs[j*4+1])*g);
            xa2 += clamp100((xi2 - xs[j*4+2])*g);
            xa3 += clamp100((xi3 - xs[j*4+3])*g);
        }
    };

    for (int base = 0; base < 4096; base += 32){
        int v = sei[base + lane];
        bool hit = (v == node);
        unsigned msk = __ballot_sync(0xffffffffu, hit);
        if (hit) list[lc + __popc(msk & lmask)] = base + lane;
        lc += __popc(msk);
        if (lc >= 128){ process(lc); cnt += lc; lc = 0; }
    }
    process(lc); cnt += lc;

    float* P = g_aggp + ((size_t)(b*Nn + node)*4 + cq)*80;
    P[lane] = m0;
    P[32 + lane] = m1;
    if (lane < 8) P[64 + lane] = m2;
    if (lane == 0){
        P[72] = xa0; P[73] = xa1; P[74] = xa2; P[75] = xa3;
        P[76] = (float)cnt;
    }
}

// ---------------- K5b: combine partials (deterministic fixed order) ------------
__global__ void __launch_bounds__(256) k_agg2(const float* __restrict__ x,
                                              float* __restrict__ out_x){
    int nid = blockIdx.x*8 + (threadIdx.x >> 5);
    int lane = threadIdx.x & 31;
    const float* P = g_aggp + (size_t)nid*320;
    float m0 = P[lane]     + P[80+lane]     + P[160+lane]     + P[240+lane];
    float m1 = P[32+lane]  + P[112+lane]    + P[192+lane]     + P[272+lane];
    float* mg = g_magg + (size_t)nid*72;
    mg[lane] = m0;
    mg[32 + lane] = m1;
    if (lane < 8){
        float m2 = P[64+lane] + P[144+lane] + P[224+lane] + P[304+lane];
        mg[64 + lane] = m2;
    }
    if (lane < 4){
        float xa  = P[72+lane] + P[152+lane] + P[232+lane] + P[312+lane];
        float cnt = P[76]      + P[156]      + P[236]      + P[316];
        out_x[(size_t)nid*4 + lane] = x[(size_t)nid*4 + lane] + xa / fmaxf(cnt, 1.f);
    }
}

// ---------------- K6: z2pre = [h, magg, attr] @ Wh1 + bh1; BN2 partials --------
__global__ void __launch_bounds__(256) k_stats2(const float* __restrict__ h,
                                                const float* __restrict__ na,
                                                const float* __restrict__ Wh1,
                                                const float* __restrict__ bh1){
    __shared__ float sW[148*72];
    for (int t = threadIdx.x; t < 148*72; t += 256) sW[t] = Wh1[t];
    __syncthreads();
    int node = blockIdx.x*256 + threadIdx.x;
    const u64* Wu = (const u64*)sW;
    const u64* bu = (const u64*)bh1;
    u64 acc[NP];
#pragma unroll
    for (int p = 0; p < NP; p++) acc[p] = bu[p];
    const float* hr = h + (size_t)node*72;
#pragma unroll 4
    for (int k = 0; k < 72; k++){
        u64 f = dup2(hr[k]);
        const u64* row = Wu + k*NP;
#pragma unroll
        for (int p = 0; p < NP; p++) acc[p] = ffma2(f, row[p], acc[p]);
    }
    const float* mr = g_magg + (size_t)node*72;
#pragma unroll 4
    for (int k = 0; k < 72; k++){
        u64 f = dup2(mr[k]);
        const u64* row = Wu + (72 + k)*NP;
#pragma unroll
        for (int p = 0; p < NP; p++) acc[p] = ffma2(f, row[p], acc[p]);
    }
    const float* ar = na + (size_t)node*4;
#pragma unroll
    for (int k = 0; k < 4; k++){
        u64 f = dup2(ar[k]);
        const u64* row = Wu + (144 + k)*NP;
#pragma unroll
        for (int p = 0; p < NP; p++) acc[p] = ffma2(f, row[p], acc[p]);
    }
    u64* zo = (u64*)(g_z2 + (size_t)node*72);
#pragma unroll
    for (int p = 0; p < NP; p++) zo[p] = acc[p];

    int lane = threadIdx.x & 31, wid = threadIdx.x >> 5;
    int gw = blockIdx.x*8 + wid;
#pragma unroll
    for (int p = 0; p < NP; p++){
        float2 v = unpack2(acc[p]);
        float s0 = wred(v.x), s1 = wred(v.y);
        float q0 = wred(v.x*v.x), q1 = wred(v.y*v.y);
        if (lane == 0){
            g_part2s[(2*p)*128 + gw] = s0; g_part2s[(2*p+1)*128 + gw] = s1;
            g_part2q[(2*p)*128 + gw] = q0; g_part2q[(2*p+1)*128 + gw] = q1;
        }
    }
}

// ---------------- K7: finalize BN2 ---------------------------------------------
__global__ void k_red2(const float* __restrict__ gh, const float* __restrict__ bh){
    __shared__ float ss[128], sq[128];
    int c = blockIdx.x, t = threadIdx.x;
    ss[t] = g_part2s[c*128 + t];
    sq[t] = g_part2q[c*128 + t];
    __syncthreads();
    for (int o = 64; o; o >>= 1){
        if (t < o){ ss[t] += ss[t+o]; sq[t] += sq[t+o]; }
        __syncthreads();
    }
    if (t == 0){
        float inv = 1.f/4096.f;
        float mu = ss[0]*inv;
        float var = sq[0]*inv - mu*mu;
        float sc = gh[c]*rsqrtf(var + 1e-5f);
        g_bn2[c] = sc;
        g_bn2[72 + c] = bh[c] - mu*sc;
    }
}

// ---------------- K8: h_out -----------------------------------------------------
__global__ void __launch_bounds__(256) k_h(const float* __restrict__ h,
                                           const float* __restrict__ Wh2,
                                           const float* __restrict__ bh2,
                                           float* __restrict__ out_h){
    extern __shared__ char smraw[];
    float* sW   = (float*)smraw;   // 5184
    float* sbn  = sW + 5184;       // 144
    float* sb2  = sbn + 144;       // 72
    float* s_act= sb2 + 72;        // 72*257
    int tid = threadIdx.x;
    for (int t = tid; t < 5184; t += 256) sW[t] = Wh2[t];
    for (int t = tid; t < 144; t += 256) sbn[t] = g_bn2[t];
    for (int t = tid; t < 72; t += 256) sb2[t] = bh2[t];
    __syncthreads();
    int node = blockIdx.x*256 + tid;
    const float* zr = g_z2 + (size_t)node*72;
#pragma unroll 4
    for (int c = 0; c < 72; c++)
        s_act[c*257 + tid] = fmaxf(fmaf(zr[c], sbn[c], sbn[72+c]), 0.f);
    const u64* Wu = (const u64*)sW;
    const u64* bu = (const u64*)sb2;
    u64 acc[NP];
#pragma unroll
    for (int p = 0; p < NP; p++) acc[p] = bu[p];
#pragma unroll 4
    for (int k = 0; k < 72; k++){
        u64 f = dup2(s_act[k*257 + tid]);
        const u64* row = Wu + k*NP;
#pragma unroll
        for (int p = 0; p < NP; p++) acc[p] = ffma2(f, row[p], acc[p]);
    }
    const float* hr = h + (size_t)node*72;
    float* o = out_h + (size_t)node*72;
#pragma unroll
    for (int p = 0; p < NP; p++){
        float2 v = unpack2(acc[p]);
        o[2*p]   = hr[2*p]   + v.x;
        o[2*p+1] = hr[2*p+1] + v.y;
    }
}

// ---------------- launch ---------------------------------------------------------
#define SMEM_STATS1 81472
#define SMEM_EDGE   91008
#define SMEM_H      95616

extern "C" void kernel_launch(void* const* d_in, const int* in_sizes, int n_in,
                              void* d_out, int out_size){
    const float* h   = (const float*)d_in[0];
    const float* x   = (const float*)d_in[1];
    const int*   ei  = (const int*)d_in[2];
    const int*   ej  = (const int*)d_in[3];
    const float* na  = (const float*)d_in[4];
    const float* We1 = (const float*)d_in[5];
    const float* g1  = (const float*)d_in[6];
    const float* b1  = (const float*)d_in[7];
    const float* We2 = (const float*)d_in[8];
    const float* be2 = (const float*)d_in[9];
    const float* Wm  = (const float*)d_in[10];
    const float* bm  = (const float*)d_in[11];
    const float* Wx1 = (const float*)d_in[12];
    const float* bx1 = (const float*)d_in[13];
    const float* Wx2 = (const float*)d_in[14];
    const float* Wh1 = (const float*)d_in[15];
    const float* bh1 = (const float*)d_in[16];
    const float* gh  = (const float*)d_in[17];
    const float* bh  = (const float*)d_in[18];
    const float* Wh2 = (const float*)d_in[19];
    const float* bh2 = (const float*)d_in[20];

    float* out   = (float*)d_out;
    float* out_h = out;                 // [B,N,72]
    float* out_x = out + 294912;        // [B,N,4]
    float* out_m = out + 311296;        // [B,E,72]

    cudaFuncSetAttribute(k_stats1, cudaFuncAttributeMaxDynamicSharedMemorySize, SMEM_STATS1);
    cudaFuncSetAttribute(k_edge,   cudaFuncAttributeMaxDynamicSharedMemorySize, SMEM_EDGE);
    cudaFuncSetAttribute(k_h,      cudaFuncAttributeMaxDynamicSharedMemorySize, SMEM_H);

    k_pq    <<<16, 256>>>(h, We1);
    k_stats1<<<512, 256, SMEM_STATS1>>>(x, ei, ej, We1);
    k_red1  <<<72, 256>>>(g1, b1);
    k_edge  <<<2048, 256, SMEM_EDGE>>>(x, ei, ej, We1, We2, be2, Wm, bm, Wx1, bx1, Wx2, out_m);
    k_agg   <<<2048, 256>>>(x, ei, ej, out_m);
    k_agg2  <<<512, 256>>>(x, out_x);
    k_stats2<<<16, 256>>>(h, na, Wh1, bh1);
    k_red2  <<<72, 128>>>(gh, bh);
    k_h     <<<16, 256, SMEM_H>>>(h, Wh2, bh2, out_h);
}